// round 17
// baseline (speedup 1.0000x reference)
// GCN + EdgePool forward — R16: scan-free CSR (atomic cursor), counting fused
// into zDeg/zDedup, packed 16B adjacency entries for suitor. 21 launches.
#include <cuda_runtime.h>
#include <math.h>

#define Nn 60000
#define Ee 600000
#define AE (2*Ee)
#define Ff 384
#define Hh 6
#define Cc 10
#define Bb 8
#define TAB (1u<<21)
#define TABM (TAB-1u)
#define NT 256
#define NB ((Nn + NT - 1)/NT)

// ---------------- scratch (static device globals; no allocation) ----------------
__device__ float g_t1[Nn*Hh];
__device__ float g_acc1[Nn*Hh];
__device__ float g_h1[Nn*Hh];
__device__ float g_x1[Nn*Hh];
__device__ float g_t2[Nn*Cc];
__device__ float g_acc2[Nn*Cc];
__device__ float g_h2[Nn*Cc];
__device__ float g_x2[Nn*Cc];

__device__ int   g_degI[Nn];
__device__ int   g_hasloop[Nn];
__device__ unsigned char g_addloop[Nn];
__device__ float g_dinv[Nn];

__device__ float g_s[Nn];
__device__ float g_ex[Ee];
__device__ float g_score[Ee];

__device__ unsigned long long g_suitor[Nn];
__device__ int g_adjCnt[Nn];
__device__ int g_off[Nn];
__device__ int g_cur[Nn];
__device__ int g_cursor;
__device__ ulonglong2 g_adj[AE];      // {prio, other}

__device__ int   g_cmap[Nn];
__device__ int   g_ns[Ee];
__device__ int   g_nd[Ee];
__device__ unsigned char g_ev1[Ee];
__device__ unsigned char g_nv1[Nn];
__device__ unsigned char g_nv2[Nn];

__device__ unsigned g_hkey[TAB];
__device__ unsigned g_hval[TAB];

__device__ float g_cnt[Bb];
__device__ float g_sum[Bb*Cc];

// ---------------- helpers ----------------
__device__ __forceinline__ unsigned fkey(float f){
    unsigned b = __float_as_uint(f);
    return b ^ (((int)b >> 31) ? 0xFFFFFFFFu : 0x80000000u);
}

// ---------------- init ----------------
__global__ void zInitMain(){
    int stride = gridDim.x*blockDim.x;
    for(unsigned i = blockIdx.x*blockDim.x + threadIdx.x; i < TAB; i += stride){
        g_hkey[i] = 0xFFFFFFFFu; g_hval[i] = 0xFFFFFFFFu;
        if(i < Nn*Cc) g_acc2[i] = 0.f;
        if(i < Nn*Hh) g_acc1[i] = 0.f;
        if(i < Nn){
            g_degI[i]=0; g_hasloop[i]=0; g_s[i]=0.f;
            g_suitor[i]=0ull; g_adjCnt[i]=0;
        }
        if(i < Bb)    g_cnt[i]=0.f;
        if(i < Bb*Cc) g_sum[i]=0.f;
        if(i == 0)    g_cursor = 0;
    }
}

// ---------------- GEMM1: t1 = x @ W1  (60000x384 @ 384x6, exact fp32) ----------
__global__ void zGemm1(const float* __restrict__ x, const float* __restrict__ W1,
                       float* __restrict__ t1){
    __shared__ float Ws[Ff*Hh];
    for(int i = threadIdx.x; i < Ff*Hh; i += blockDim.x) Ws[i] = W1[i];
    __syncthreads();
    int warp = threadIdx.x >> 5, lane = threadIdx.x & 31;
    int row = blockIdx.x*8 + warp;
    if(row >= Nn) return;
    const float* xr = x + (size_t)row*Ff;
    float a0=0,a1=0,a2=0,a3=0,a4=0,a5=0;
    for(int k = lane; k < Ff; k += 32){
        float xv = xr[k];
        const float* w = Ws + k*Hh;
        a0 += xv*w[0]; a1 += xv*w[1]; a2 += xv*w[2];
        a3 += xv*w[3]; a4 += xv*w[4]; a5 += xv*w[5];
    }
    #pragma unroll
    for(int off = 16; off; off >>= 1){
        a0 += __shfl_down_sync(0xffffffffu, a0, off);
        a1 += __shfl_down_sync(0xffffffffu, a1, off);
        a2 += __shfl_down_sync(0xffffffffu, a2, off);
        a3 += __shfl_down_sync(0xffffffffu, a3, off);
        a4 += __shfl_down_sync(0xffffffffu, a4, off);
        a5 += __shfl_down_sync(0xffffffffu, a5, off);
    }
    if(lane == 0){
        float* o = t1 + (size_t)row*Hh;
        o[0]=a0; o[1]=a1; o[2]=a2; o[3]=a3; o[4]=a4; o[5]=a5;
    }
}

// ---------------- stage-1 degree + adjacency counts ----------------
__global__ void zDeg(const int* __restrict__ sA, const int* __restrict__ dA){
    int e = blockIdx.x*blockDim.x + threadIdx.x;
    if(e >= Ee) return;
    int s = sA[e], d = dA[e];
    atomicAdd(&g_degI[d], 1);
    if(s == d) g_hasloop[d] = 1;
    atomicAdd(&g_adjCnt[s], 1);
    if(d != s) atomicAdd(&g_adjCnt[d], 1);
}

// stage-1: dinv + CSR offset assignment (unordered cursor)
__global__ void zDinv1(){
    int v = blockIdx.x*blockDim.x + threadIdx.x;
    if(v >= Nn) return;
    int add = g_hasloop[v] ? 0 : 1;
    g_addloop[v] = (unsigned char)add;
    int dg = g_degI[v] + add;
    g_dinv[v] = (dg > 0) ? 1.0f/sqrtf((float)dg) : 0.0f;
    int c = g_adjCnt[v];
    int off = c ? atomicAdd(&g_cursor, c) : 0;
    g_off[v] = off; g_cur[v] = off;
}

// ---------------- layer-2 fused: dinv + offsets + t2 = x1 @ W2 ------------------
__global__ void zDinvGemm2(const unsigned char* __restrict__ nv,
                           const float* __restrict__ x1, const float* __restrict__ W2,
                           float* __restrict__ t2){
    int v = blockIdx.x*blockDim.x + threadIdx.x;
    if(v >= Nn) return;
    int add = (nv[v] && !g_hasloop[v]) ? 1 : 0;
    g_addloop[v] = (unsigned char)add;
    int dg = g_degI[v] + add;
    g_dinv[v] = (dg > 0) ? 1.0f/sqrtf((float)dg) : 0.0f;
    int c = g_adjCnt[v];
    int off = c ? atomicAdd(&g_cursor, c) : 0;
    g_off[v] = off; g_cur[v] = off;
    float xr[Hh];
    #pragma unroll
    for(int j = 0; j < Hh; j++) xr[j] = x1[v*Hh + j];
    #pragma unroll
    for(int c2 = 0; c2 < Cc; c2++){
        float a = 0.f;
        #pragma unroll
        for(int j = 0; j < Hh; j++) a += xr[j]*W2[j*Cc + c2];
        t2[v*Cc + c2] = a;
    }
}

template<int FD>
__global__ void zAgg(const int* __restrict__ sA, const int* __restrict__ dA,
                     const unsigned char* __restrict__ ev,
                     const float* __restrict__ t, float* __restrict__ acc){
    int e = blockIdx.x*blockDim.x + threadIdx.x;
    if(e >= Ee) return;
    if(ev && !ev[e]) return;
    int s = sA[e], d = dA[e];
    float c = g_dinv[s]*g_dinv[d];
    #pragma unroll
    for(int j = 0; j < FD; j++)
        atomicAdd(&acc[(size_t)d*FD + j], t[(size_t)s*FD + j]*c);
}

template<int FD, bool RELU>
__global__ void zFinishGcn(const float* __restrict__ acc, const float* __restrict__ t,
                           const float* __restrict__ bias, float* __restrict__ out){
    int v = blockIdx.x*blockDim.x + threadIdx.x;
    if(v >= Nn) return;
    float di = g_dinv[v];
    float al = g_addloop[v] ? di*di : 0.0f;
    #pragma unroll
    for(int j = 0; j < FD; j++){
        float o = acc[(size_t)v*FD + j] + al*t[(size_t)v*FD + j] + bias[j];
        out[(size_t)v*FD + j] = RELU ? fmaxf(o, 0.0f) : o;
    }
}

// ---------------- edge pool pass 1: raw -> exp -> segment sum -------------------
// (softmax max-shift eliminated: score invariant to it; raw is O(1))
template<int FD>
__global__ void zPass1(const float* __restrict__ xf, const int* __restrict__ sA,
                       const int* __restrict__ dA, const unsigned char* __restrict__ ev,
                       const float* __restrict__ Wp, const float* __restrict__ bp){
    int e = blockIdx.x*blockDim.x + threadIdx.x;
    if(e >= Ee) return;
    bool valid = ev ? (ev[e] != 0) : true;
    float exv = 0.0f;
    if(valid){
        int s = sA[e], d = dA[e];
        float r = bp[0];
        #pragma unroll
        for(int j = 0; j < FD; j++) r += xf[(size_t)s*FD + j]*Wp[j];
        #pragma unroll
        for(int j = 0; j < FD; j++) r += xf[(size_t)d*FD + j]*Wp[FD + j];
        exv = expf(r);
        atomicAdd(&g_s[d], exv);
    }
    g_ex[e] = exv;
}

// ---------------- pass 2: score + prio + CSR adjacency fill (packed 16B) --------
__global__ void zFill(const int* __restrict__ sA, const int* __restrict__ dA,
                      const unsigned char* __restrict__ ev){
    int e = blockIdx.x*blockDim.x + threadIdx.x;
    if(e >= Ee) return;
    bool valid = ev ? (ev[e] != 0) : true;
    if(!valid) return;
    int s = sA[e], d = dA[e];
    float sv = g_s[d];
    float sc = g_ex[e]/((sv > 0.f) ? sv : 1.f) + 0.5f;
    g_score[e] = sc;
    // total priority = (score desc, edge index asc) == stable argsort(-score)
    unsigned long long p = ((unsigned long long)fkey(sc) << 32)
                         | (unsigned long long)(0xFFFFFFFFu - (unsigned)e);
    int slot = atomicAdd(&g_cur[s], 1);
    g_adj[slot] = make_ulonglong2(p, (unsigned long long)(unsigned)d);
    if(d != s){
        slot = atomicAdd(&g_cur[d], 1);
        g_adj[slot] = make_ulonglong2(p, (unsigned long long)(unsigned)s);
    }
}

// ---------------- Suitor matching (== sequential greedy; no barriers) ----------
// Single-ownership: a node is re-processed only by the thread that displaced its
// accepted proposal; suitor values are monotonically increasing (atomicMax), so
// stale volatile reads are <= current and can never cause a false skip.
__global__ void zSuitor(const int* __restrict__ sA, const int* __restrict__ dA){
    int u = blockIdx.x*blockDim.x + threadIdx.x;
    if(u >= Nn) return;
    while(true){
        int lo = g_off[u], hi = lo + g_adjCnt[u];
        unsigned long long best = 0ull; int bestv = -1;
        for(int i = lo; i < hi; i++){
            ulonglong2 a = g_adj[i];
            if(a.x <= best) continue;
            int w = (int)a.y;
            if(a.x > *((volatile unsigned long long*)&g_suitor[w])){ best = a.x; bestv = w; }
        }
        if(bestv < 0) break;
        unsigned long long old = atomicMax(&g_suitor[bestv], best);
        if(old < best){
            if(old == 0ull) break;
            int e = (int)(0xFFFFFFFFu - (unsigned)(old & 0xFFFFFFFFull));
            int s = sA[e], d = dA[e];
            u = (s == bestv) ? d : s;   // take over displaced proposer
        }
        // else: lost the race — rescan the same u
    }
}

// ---------------- pool node + match extraction (+ next-stage resets) -----------
template<int FD, bool HAVENV, bool RESETNEXT>
__global__ void zPoolNode(const float* __restrict__ xin, float* __restrict__ xout,
                          const unsigned char* __restrict__ nvin, unsigned char* __restrict__ nvout,
                          const int* __restrict__ sA, const int* __restrict__ dA){
    int v = blockIdx.x*blockDim.x + threadIdx.x;
    if(v >= Nn) return;
    unsigned long long p = g_suitor[v];
    float scl = 1.0f; int prt = -1; bool deadv = false; int cm = v;
    if(p != 0ull){
        int e = (int)(0xFFFFFFFFu - (unsigned)(p & 0xFFFFFFFFull));
        int s = sA[e], d = dA[e];
        if(g_suitor[s] == p && g_suitor[d] == p){    // mutual => matched via e
            if(v == s){ scl = g_score[e]; if(d != s) prt = d; }
            else if(v == d && s != d){ deadv = true; cm = s; }
        }
    }
    bool nvbase = HAVENV ? (nvin[v] != 0) : true;
    unsigned char nv = (nvbase && !deadv) ? 1 : 0;
    nvout[v] = nv;
    g_cmap[v] = cm;
    #pragma unroll
    for(int j = 0; j < FD; j++){
        float val = xin[(size_t)v*FD + j] + ((prt >= 0) ? xin[(size_t)prt*FD + j] : 0.0f);
        xout[(size_t)v*FD + j] = nv ? val*scl : 0.0f;
    }
    if(RESETNEXT){
        g_suitor[v] = 0ull; g_s[v] = 0.f; g_adjCnt[v] = 0;
        g_degI[v] = 0; g_hasloop[v] = 0;
        if(v == 0) g_cursor = 0;
    }
}

// ---------------- remap + dedup (hash; representative = min original index) ------
__global__ void zRemapHash(const int* __restrict__ sA, const int* __restrict__ dA){
    int e = blockIdx.x*blockDim.x + threadIdx.x;
    if(e >= Ee) return;
    int ns = g_cmap[sA[e]];
    int nd = g_cmap[dA[e]];
    g_ns[e] = ns; g_nd[e] = nd;
    unsigned key = (unsigned)ns*60000u + (unsigned)nd;
    unsigned h = (key*2654435761u) & TABM;
    while(true){
        unsigned old = atomicCAS(&g_hkey[h], 0xFFFFFFFFu, key);
        if(old == 0xFFFFFFFFu || old == key){
            atomicMin(&g_hval[h], (unsigned)e);
            break;
        }
        h = (h + 1u) & TABM;
    }
}

// dedup + layer-2 degree AND adjacency counting fused
__global__ void zDedup(){
    int e = blockIdx.x*blockDim.x + threadIdx.x;
    if(e >= Ee) return;
    int ns = g_ns[e], nd = g_nd[e];
    unsigned key = (unsigned)ns*60000u + (unsigned)nd;
    unsigned h = (key*2654435761u) & TABM;
    while(g_hkey[h] != key) h = (h + 1u) & TABM;
    unsigned char ev = (g_hval[h] == (unsigned)e) ? 1 : 0;
    g_ev1[e] = ev;
    if(ev){
        atomicAdd(&g_degI[nd], 1);
        if(ns == nd) g_hasloop[nd] = 1;
        atomicAdd(&g_adjCnt[ns], 1);
        if(nd != ns) atomicAdd(&g_adjCnt[nd], 1);
    }
}

// ---------------- final pooling + log_softmax ----------------
__global__ void zPoolBatch(const int* __restrict__ batch, const float* __restrict__ x2){
    __shared__ float sc[Bb];
    __shared__ float ss[Bb*Cc];
    int t = threadIdx.x;
    if(t < Bb)    sc[t] = 0.f;
    if(t < Bb*Cc) ss[t] = 0.f;
    __syncthreads();
    for(int v = blockIdx.x*blockDim.x + t; v < Nn; v += gridDim.x*blockDim.x){
        if(g_nv2[v]){
            int b = batch[v];
            atomicAdd(&sc[b], 1.0f);
            #pragma unroll
            for(int c = 0; c < Cc; c++)
                atomicAdd(&ss[b*Cc + c], x2[(size_t)v*Cc + c]);
        }
    }
    __syncthreads();
    if(t < Bb)    atomicAdd(&g_cnt[t], sc[t]);
    if(t < Bb*Cc) atomicAdd(&g_sum[t], ss[t]);
}

__global__ void zFinal(float* __restrict__ out){
    __shared__ float gs[Bb*Cc];
    __shared__ float lse[Bb];
    int t = threadIdx.x;
    if(t < Bb*Cc) gs[t] = g_sum[t]/g_cnt[t/Cc];
    __syncthreads();
    if(t < Bb){
        float m = -1e30f;
        for(int c = 0; c < Cc; c++) m = fmaxf(m, gs[t*Cc + c]);
        float s = 0.f;
        for(int c = 0; c < Cc; c++) s += expf(gs[t*Cc + c] - m);
        lse[t] = m + logf(s);
    }
    __syncthreads();
    if(t < Bb*Cc) out[t] = gs[t] - lse[t/Cc];
}

// ---------------- launch ----------------
extern "C" void kernel_launch(void* const* d_in, const int* in_sizes, int n_in,
                              void* d_out, int out_size){
    (void)in_sizes; (void)n_in; (void)out_size;
    const float* x    = (const float*)d_in[0];
    const int*   src  = (const int*)  d_in[1];
    const int*   dst  = (const int*)  d_in[2];
    const int*   bat  = (const int*)  d_in[3];
    const float* W1   = (const float*)d_in[4];
    const float* b1   = (const float*)d_in[5];
    const float* W2   = (const float*)d_in[6];
    const float* b2   = (const float*)d_in[7];
    const float* Wp1  = (const float*)d_in[8];
    const float* bp1  = (const float*)d_in[9];
    const float* Wp2  = (const float*)d_in[10];
    const float* bp2  = (const float*)d_in[11];
    float* out = (float*)d_out;

    const int EB  = (Ee + NT - 1)/NT;
    const int IB  = (int)((TAB + NT - 1)/NT);

    // every device-global pointer passed as a kernel ARG must come from
    // cudaGetSymbolAddress (host symbol == host shadow under ATS!)
    float *pT1, *pAcc1, *pH1, *pX1, *pT2, *pAcc2, *pH2, *pX2;
    cudaGetSymbolAddress((void**)&pT1,   g_t1);
    cudaGetSymbolAddress((void**)&pAcc1, g_acc1);
    cudaGetSymbolAddress((void**)&pH1,   g_h1);
    cudaGetSymbolAddress((void**)&pX1,   g_x1);
    cudaGetSymbolAddress((void**)&pT2,   g_t2);
    cudaGetSymbolAddress((void**)&pAcc2, g_acc2);
    cudaGetSymbolAddress((void**)&pH2,   g_h2);
    cudaGetSymbolAddress((void**)&pX2,   g_x2);
    int *pNs, *pNd;
    cudaGetSymbolAddress((void**)&pNs, g_ns);
    cudaGetSymbolAddress((void**)&pNd, g_nd);
    unsigned char *pEv1, *pNv1, *pNv2;
    cudaGetSymbolAddress((void**)&pEv1, g_ev1);
    cudaGetSymbolAddress((void**)&pNv1, g_nv1);
    cudaGetSymbolAddress((void**)&pNv2, g_nv2);

    zInitMain<<<IB, NT>>>();

    // ---- GCN layer 1 + relu ----
    zGemm1<<<Nn/8, NT>>>(x, W1, pT1);
    zDeg<<<EB, NT>>>(src, dst);
    zDinv1<<<NB, NT>>>();
    zAgg<Hh><<<EB, NT>>>(src, dst, nullptr, pT1, pAcc1);
    zFinishGcn<Hh, true><<<NB, NT>>>(pAcc1, pT1, b1, pH1);

    // ---- EdgePool 1 (suitor) ----
    zPass1<Hh><<<EB, NT>>>(pH1, src, dst, nullptr, Wp1, bp1);
    zFill<<<EB, NT>>>(src, dst, nullptr);
    zSuitor<<<NB, NT>>>(src, dst);
    zPoolNode<Hh, false, true><<<NB, NT>>>(pH1, pX1, nullptr, pNv1, src, dst);

    // ---- remap + dedup (+ layer-2 degrees/adjacency) ----
    zRemapHash<<<EB, NT>>>(src, dst);
    zDedup<<<EB, NT>>>();

    // ---- GCN layer 2 (dinv + offsets fused with gemm2) ----
    zDinvGemm2<<<NB, NT>>>(pNv1, pX1, W2, pT2);
    zAgg<Cc><<<EB, NT>>>(pNs, pNd, pEv1, pT2, pAcc2);
    zFinishGcn<Cc, false><<<NB, NT>>>(pAcc2, pT2, b2, pH2);

    // ---- EdgePool 2 (suitor) ----
    zPass1<Cc><<<EB, NT>>>(pH2, pNs, pNd, pEv1, Wp2, bp2);
    zFill<<<EB, NT>>>(pNs, pNd, pEv1);
    zSuitor<<<NB, NT>>>(pNs, pNd);
    zPoolNode<Cc, true, false><<<NB, NT>>>(pH2, pX2, pNv1, pNv2, pNs, pNd);

    // ---- mean pool + log_softmax ----
    zPoolBatch<<<NB, NT>>>(bat, pX2);
    zFinal<<<1, 128>>>(out);
}